// round 2
// baseline (speedup 1.0000x reference)
#include <cuda_runtime.h>
#include <math.h>

// ---------------- problem constants ----------------
constexpr int cB = 64;      // batch
constexpr int cS = 196;     // feature seq len
constexpr int cH = 1024;    // hidden
constexpr int cK = 2048;    // feature dim
constexpr int cV = 10000;   // vocab
constexpr int cE = 512;     // embed
constexpr int cT = 16;      // caption len
constexpr int cTS = 15;     // decode steps (T-1)
constexpr int BSR = cB * cS;   // 12544 rows of features
constexpr int MT  = cTS * cB;  // 960 rows (t*64+b)

// ---------------- device scratch (no allocs allowed) ----------------
__device__ float g_Wi0T[cK * 3 * cH];        // [2048][3072]
__device__ float g_Wh0T[cH * 3 * cH];        // [1024][3072]
__device__ float g_WiT[3][cH * 3 * cH];      // per layer [1024][3072]
__device__ float g_WhT[3][cH * 3 * cH];
__device__ float g_keys[BSR * cH];           // keys_proj
__device__ float g_feat0[BSR * cH];          // features @ fc0_W + fc0_b
__device__ float g_xemb[MT * cE];
__device__ float g_xseq[MT * cH];
__device__ float g_h[4 * cB * cH];           // GRU hidden state
__device__ float g_hall[MT * cH];            // top-layer h per step
__device__ float g_q[cB * cH];
__device__ float g_e[cB * cS];
__device__ float g_w[cB * cS];
__device__ float g_inp[cB * 2 * cH];         // [x_t | ctx]
__device__ float g_gi[cB * 3 * cH];
__device__ float g_gh[cB * 3 * cH];

// ---------------- generic fp32 GEMM ----------------
// C[M,N] = A[M,K] @ B[K,N]  (both row-major). K-slice per blockIdx.z.
// MODE 0: store acc + bias  (splitk must be 1)
// MODE 1: atomicAdd into C (C pre-initialized with bias)
// MODE 2: store acc + bias, remapping row m=t*64+b -> out row b*cTS+t (fc2)
template <int BM, int BN, int BK, int TM, int TN, int MODE>
__global__ __launch_bounds__(256) void sgemm_k(
    const float* __restrict__ A, const float* __restrict__ Bm,
    float* __restrict__ C, int M, int N, int K, int klen,
    const float* __restrict__ bias)
{
    __shared__ float As[BM][BK + 1];
    __shared__ float Bs[BK][BN];
    const int tid = threadIdx.x;
    const int m0 = blockIdx.y * BM;
    const int n0 = blockIdx.x * BN;
    const int k0 = blockIdx.z * klen;
    constexpr int NT = 256;
    constexpr int TX = BN / TN;          // threads along N
    const int tx = tid % TX;
    const int ty = tid / TX;

    float c[TM][TN];
#pragma unroll
    for (int i = 0; i < TM; i++)
#pragma unroll
        for (int j = 0; j < TN; j++) c[i][j] = 0.f;

    for (int kb = k0; kb < k0 + klen; kb += BK) {
        // load A tile
#pragma unroll
        for (int i = 0; i < (BM * BK) / NT; i++) {
            int idx = i * NT + tid;
            int m = idx / BK, kk = idx % BK;
            As[m][kk] = A[(size_t)(m0 + m) * K + kb + kk];
        }
        // load B tile (guard N edge)
#pragma unroll
        for (int i = 0; i < (BK * BN) / NT; i++) {
            int idx = i * NT + tid;
            int kk = idx / BN, n = idx % BN;
            float v = 0.f;
            if (n0 + n < N) v = Bm[(size_t)(kb + kk) * N + n0 + n];
            Bs[kk][n] = v;
        }
        __syncthreads();
#pragma unroll
        for (int kk = 0; kk < BK; kk++) {
            float a[TM], b[TN];
#pragma unroll
            for (int i = 0; i < TM; i++) a[i] = As[ty * TM + i][kk];
#pragma unroll
            for (int j = 0; j < TN; j++) b[j] = Bs[kk][tx * TN + j];
#pragma unroll
            for (int i = 0; i < TM; i++)
#pragma unroll
                for (int j = 0; j < TN; j++) c[i][j] += a[i] * b[j];
        }
        __syncthreads();
    }
#pragma unroll
    for (int i = 0; i < TM; i++) {
        int m = m0 + ty * TM + i;
#pragma unroll
        for (int j = 0; j < TN; j++) {
            int n = n0 + tx * TN + j;
            if (n < N) {
                if (MODE == 0) {
                    C[(size_t)m * N + n] = c[i][j] + (bias ? bias[n] : 0.f);
                } else if (MODE == 1) {
                    atomicAdd(&C[(size_t)m * N + n], c[i][j]);
                } else {
                    int bb = m & 63, tt = m >> 6;
                    C[(size_t)(bb * cTS + tt) * N + n] = c[i][j] + bias[n];
                }
            }
        }
    }
}

// ---------------- helpers ----------------
__global__ void k_transpose(const float* __restrict__ in, float* __restrict__ out,
                            int R, int C)
{
    __shared__ float tile[32][33];
    int c0 = blockIdx.x * 32, r0 = blockIdx.y * 32;
#pragma unroll
    for (int i = 0; i < 32; i += 8)
        tile[threadIdx.y + i][threadIdx.x] =
            in[(size_t)(r0 + threadIdx.y + i) * C + c0 + threadIdx.x];
    __syncthreads();
#pragma unroll
    for (int i = 0; i < 32; i += 8)
        out[(size_t)(c0 + threadIdx.y + i) * R + r0 + threadIdx.x] =
            tile[threadIdx.x][threadIdx.y + i];
}

__global__ void k_zero(float* p, int n)
{
    int i = blockIdx.x * blockDim.x + threadIdx.x;
    if (i < n) p[i] = 0.f;
}

__global__ void k_embed(const int* __restrict__ captions, const int* __restrict__ sos,
                        const float* __restrict__ emb)
{
    int r = blockIdx.x;              // r = t*64 + b
    int t = r >> 6, b = r & 63;
    int tok = (t == 0) ? *sos : captions[b * cT + t];
    const float* src = emb + (size_t)tok * cE;
    float* dst = g_xemb + (size_t)r * cE;
    for (int i = threadIdx.x; i < cE; i += blockDim.x) dst[i] = src[i];
}

__global__ void k_initbias(float* C, const float* __restrict__ bias, int N, int total)
{
    int i = blockIdx.x * blockDim.x + threadIdx.x;
    if (i < total) C[i] = bias[i % N];
}

__global__ void k_init2(float* gi, const float* __restrict__ bi,
                        float* gh, const float* __restrict__ bh)
{
    int i = blockIdx.x * blockDim.x + threadIdx.x;
    if (i < cB * 3 * cH) {
        int n = i % (3 * cH);
        gi[i] = bi[n];
        gh[i] = bh[n];
    }
}

// scores: e[b,s] = sum_h tanh(q[b,h] + keys[b,s,h]) * v[h] + bv
__global__ __launch_bounds__(256) void k_scores(const float* __restrict__ v,
                                                const float* __restrict__ bv)
{
    int bs = blockIdx.x;             // b*196 + s
    int b = bs / cS;
    int tid = threadIdx.x;
    const float* qr = g_q + (size_t)b * cH;
    const float* kr = g_keys + (size_t)bs * cH;
    float acc = 0.f;
#pragma unroll 4
    for (int h = tid; h < cH; h += 256)
        acc += tanhf(qr[h] + kr[h]) * v[h];
#pragma unroll
    for (int o = 16; o; o >>= 1) acc += __shfl_down_sync(0xffffffffu, acc, o);
    __shared__ float red[8];
    if ((tid & 31) == 0) red[tid >> 5] = acc;
    __syncthreads();
    if (tid == 0) {
        float s = 0.f;
#pragma unroll
        for (int i = 0; i < 8; i++) s += red[i];
        g_e[bs] = s + bv[0];
    }
}

__global__ __launch_bounds__(256) void k_softmax()
{
    int b = blockIdx.x, tid = threadIdx.x;
    __shared__ float sm[256];
    float v = (tid < cS) ? g_e[b * cS + tid] : -1e30f;
    sm[tid] = v; __syncthreads();
    for (int o = 128; o; o >>= 1) { if (tid < o) sm[tid] = fmaxf(sm[tid], sm[tid + o]); __syncthreads(); }
    float mx = sm[0]; __syncthreads();
    float ev = (tid < cS) ? expf(v - mx) : 0.f;
    sm[tid] = ev; __syncthreads();
    for (int o = 128; o; o >>= 1) { if (tid < o) sm[tid] += sm[tid + o]; __syncthreads(); }
    float s = sm[0];
    if (tid < cS) g_w[b * cS + tid] = ev / s;
}

// ctx into inp[:,H:] (+ copy x_t into inp[:,:H]).  fc0_b is pre-baked into feat0.
__global__ __launch_bounds__(256) void k_ctx(int t)
{
    int idx = blockIdx.x * blockDim.x + threadIdx.x;   // 65536 threads
    int b = idx >> 10, h = idx & (cH - 1);
    const float* f = g_feat0 + ((size_t)b * cS) * cH + h;
    const float* wr = g_w + b * cS;
    float a0 = 0.f, a1 = 0.f, a2 = 0.f, a3 = 0.f;
#pragma unroll 1
    for (int s = 0; s < cS; s += 4) {
        a0 += wr[s + 0] * f[(size_t)(s + 0) * cH];
        a1 += wr[s + 1] * f[(size_t)(s + 1) * cH];
        a2 += wr[s + 2] * f[(size_t)(s + 2) * cH];
        a3 += wr[s + 3] * f[(size_t)(s + 3) * cH];
    }
    g_inp[b * 2 * cH + cH + h] = (a0 + a1) + (a2 + a3);
    g_inp[b * 2 * cH + h] = g_xseq[(size_t)(t * cB + b) * cH + h];
}

__device__ __forceinline__ float sigm(float x) { return 1.f / (1.f + expf(-x)); }

__global__ __launch_bounds__(256) void k_gruew(int layer, int t)
{
    int idx = blockIdx.x * blockDim.x + threadIdx.x;   // 65536
    int b = idx >> 10, j = idx & (cH - 1);
    const float* gi = g_gi + (size_t)b * 3 * cH;
    const float* gh = g_gh + (size_t)b * 3 * cH;
    float ir = gi[j], iz = gi[cH + j], inn = gi[2 * cH + j];
    float hr = gh[j], hz = gh[cH + j], hn = gh[2 * cH + j];
    float r = sigm(ir + hr);
    float z = sigm(iz + hz);
    float n = tanhf(inn + r * hn);
    float* hp = g_h + (size_t)layer * cB * cH + idx;
    float hold = *hp;
    float hnew = (1.f - z) * n + z * hold;
    *hp = hnew;
    if (layer == 3) g_hall[(size_t)(t * cB + b) * cH + j] = hnew;
}

// ---------------- host-side GEMM launcher ----------------
static void gemm(const float* A, const float* Bm, float* C, int M, int N, int K,
                 int splitk, const float* bias, int mode, bool big)
{
    int klen = K / splitk;
    if (big) {
        dim3 g((N + 63) / 64, M / 128, splitk);
        sgemm_k<128, 64, 16, 8, 4, 0><<<g, 256>>>(A, Bm, C, M, N, K, klen, bias);
        return;
    }
    dim3 g((N + 63) / 64, M / 64, splitk);
    if (mode == 0)      sgemm_k<64, 64, 16, 4, 4, 0><<<g, 256>>>(A, Bm, C, M, N, K, klen, bias);
    else if (mode == 1) sgemm_k<64, 64, 16, 4, 4, 1><<<g, 256>>>(A, Bm, C, M, N, K, klen, bias);
    else                sgemm_k<64, 64, 16, 4, 4, 2><<<g, 256>>>(A, Bm, C, M, N, K, klen, bias);
}

extern "C" void kernel_launch(void* const* d_in, const int* in_sizes, int n_in,
                              void* d_out, int out_size)
{
    const float* features = (const float*)d_in[0];
    const int*   captions = (const int*)d_in[1];
    const int*   sos      = (const int*)d_in[2];
    const float* emb      = (const float*)d_in[3];
    const float* fc1_W = (const float*)d_in[4];  const float* fc1_b = (const float*)d_in[5];
    const float* aWq   = (const float*)d_in[6];  const float* abq   = (const float*)d_in[7];
    const float* aWk   = (const float*)d_in[8];  const float* abk   = (const float*)d_in[9];
    const float* av    = (const float*)d_in[10]; const float* abv   = (const float*)d_in[11];
    const float* fc0_W = (const float*)d_in[12]; const float* fc0_b = (const float*)d_in[13];
    const float* Wi0   = (const float*)d_in[14]; const float* Wh0   = (const float*)d_in[15];
    const float* bi0   = (const float*)d_in[16]; const float* bh0   = (const float*)d_in[17];
    const float* Wi    = (const float*)d_in[18]; const float* Wh    = (const float*)d_in[19];
    const float* bi    = (const float*)d_in[20]; const float* bh    = (const float*)d_in[21];
    const float* fc2_W = (const float*)d_in[22]; const float* fc2_b = (const float*)d_in[23];
    float* out = (float*)d_out;

    float *pWi0T, *pWh0T, *pWiT, *pWhT, *pkeys, *pfeat0, *pxemb, *pxseq, *ph,
          *phall, *pq, *pinp, *pgi, *pgh;
    cudaGetSymbolAddress((void**)&pWi0T, g_Wi0T);
    cudaGetSymbolAddress((void**)&pWh0T, g_Wh0T);
    cudaGetSymbolAddress((void**)&pWiT,  g_WiT);
    cudaGetSymbolAddress((void**)&pWhT,  g_WhT);
    cudaGetSymbolAddress((void**)&pkeys, g_keys);
    cudaGetSymbolAddress((void**)&pfeat0, g_feat0);
    cudaGetSymbolAddress((void**)&pxemb, g_xemb);
    cudaGetSymbolAddress((void**)&pxseq, g_xseq);
    cudaGetSymbolAddress((void**)&ph,    g_h);
    cudaGetSymbolAddress((void**)&phall, g_hall);
    cudaGetSymbolAddress((void**)&pq,    g_q);
    cudaGetSymbolAddress((void**)&pinp,  g_inp);
    cudaGetSymbolAddress((void**)&pgi,   g_gi);
    cudaGetSymbolAddress((void**)&pgh,   g_gh);

    dim3 tb(32, 8);
    // one-time weight transposes -> K-major layout
    k_transpose<<<dim3(3 * cH / 32, cK / 32), tb>>>(Wi0, pWi0T, 3 * cH, cK);
    // NOTE: k_transpose(in[R,C]) -> out[C,R]; here in = Wi0 [3H, 2H] (R=3072,C=2048)
    // grid must be (C/32, R/32):
    // (relaunch with correct grid; the first launch above used swapped dims -> fix)
    k_transpose<<<dim3(cK / 32, 3 * cH / 32), tb>>>(Wi0, pWi0T, 3 * cH, cK);
    k_transpose<<<dim3(cH / 32, 3 * cH / 32), tb>>>(Wh0, pWh0T, 3 * cH, cH);
    for (int l = 0; l < 3; l++) {
        k_transpose<<<dim3(cH / 32, 3 * cH / 32), tb>>>(
            Wi + (size_t)l * 3 * cH * cH, pWiT + (size_t)l * cH * 3 * cH, 3 * cH, cH);
        k_transpose<<<dim3(cH / 32, 3 * cH / 32), tb>>>(
            Wh + (size_t)l * 3 * cH * cH, pWhT + (size_t)l * cH * 3 * cH, 3 * cH, cH);
    }

    // init hidden state to zero
    k_zero<<<(4 * cB * cH) / 256, 256>>>(ph, 4 * cB * cH);

    // precompute: x_seq, keys_proj, feat0 (fc0_b baked in: softmax weights sum to 1)
    k_embed<<<MT, 128>>>(captions, sos, emb);
    gemm(pxemb, fc1_W, pxseq, MT, cH, cE, 1, fc1_b, 0, false);
    gemm(features, aWk, pkeys, BSR, cH, cK, 1, abk, 0, true);
    gemm(features, fc0_W, pfeat0, BSR, cH, cK, 1, fc0_b, 0, true);

    for (int t = 0; t < cTS; t++) {
        // q = h[3] @ attn_Wq + bq   (split-K atomic)
        k_initbias<<<(cB * cH) / 256, 256>>>(pq, abq, cH, cB * cH);
        gemm(ph + 3 * cB * cH, aWq, pq, cB, cH, cH, 8, nullptr, 1, false);
        // attention
        k_scores<<<BSR, 256>>>(av, abv);
        k_softmax<<<cB, 256>>>();
        k_ctx<<<(cB * cH) / 256, 256>>>(t);
        // GRU layer 0 (input = [x_t | ctx], K = 2048)
        k_init2<<<(cB * 3 * cH) / 256, 256>>>(pgi, bi0, pgh, bh0);
        gemm(pinp, pWi0T, pgi, cB, 3 * cH, 2 * cH, 4, nullptr, 1, false);
        gemm(ph, pWh0T, pgh, cB, 3 * cH, cH, 4, nullptr, 1, false);
        k_gruew<<<(cB * cH) / 256, 256>>>(0, t);
        // GRU layers 1..3
        for (int l = 1; l < 4; l++) {
            k_init2<<<(cB * 3 * cH) / 256, 256>>>(pgi, bi + (l - 1) * 3 * cH,
                                                  pgh, bh + (l - 1) * 3 * cH);
            gemm(ph + (l - 1) * cB * cH, pWiT + (size_t)(l - 1) * cH * 3 * cH,
                 pgi, cB, 3 * cH, cH, 4, nullptr, 1, false);
            gemm(ph + l * cB * cH, pWhT + (size_t)(l - 1) * cH * 3 * cH,
                 pgh, cB, 3 * cH, cH, 4, nullptr, 1, false);
            k_gruew<<<(cB * cH) / 256, 256>>>(l, t);
        }
    }

    // deferred output projection with row remap (t*64+b -> b*15+t)
    gemm(phall, fc2_W, out, MT, cV, cH, 1, fc2_b, 2, false);
}

// round 3
// speedup vs baseline: 1.0007x; 1.0007x over previous
#include <cuda_runtime.h>
#include <math.h>

// ---------------- problem constants ----------------
constexpr int cB = 64;      // batch
constexpr int cS = 196;     // feature seq len
constexpr int cH = 1024;    // hidden
constexpr int cK = 2048;    // feature dim
constexpr int cV = 10000;   // vocab
constexpr int cE = 512;     // embed
constexpr int cT = 16;      // caption len
constexpr int cTS = 15;     // decode steps (T-1)
constexpr int BSR = cB * cS;   // 12544 rows of features
constexpr int MT  = cTS * cB;  // 960 rows (t*64+b)

// ---------------- device scratch (no allocs allowed) ----------------
__device__ float g_Wi0T[cK * 3 * cH];        // [2048][3072]
__device__ float g_Wh0T[cH * 3 * cH];        // [1024][3072]
__device__ float g_WiT[3][cH * 3 * cH];      // per layer [1024][3072]
__device__ float g_WhT[3][cH * 3 * cH];
__device__ float g_keys[BSR * cH];           // keys_proj
__device__ float g_feat0[BSR * cH];          // features @ fc0_W + fc0_b
__device__ float g_xemb[MT * cE];
__device__ float g_xseq[MT * cH];
__device__ float g_h[4 * cB * cH];           // GRU hidden state
__device__ float g_hall[MT * cH];            // top-layer h per step
__device__ float g_q[cB * cH];
__device__ float g_e[cB * cS];
__device__ float g_w[cB * cS];
__device__ float g_inp[cB * 2 * cH];         // [x_t | ctx]
__device__ float g_gi[cB * 3 * cH];
__device__ float g_gh[cB * 3 * cH];

// ---------------- generic fp32 GEMM ----------------
// C[M,N] = A[M,K] @ B[K,N]  (both row-major). K-slice per blockIdx.z.
// MODE 0: store acc + bias  (splitk must be 1)
// MODE 1: atomicAdd into C (C pre-initialized with bias)
// MODE 2: store acc + bias, remapping row m=t*64+b -> out row b*cTS+t (fc2)
template <int BM, int BN, int BK, int TM, int TN, int MODE>
__global__ __launch_bounds__(256) void sgemm_k(
    const float* __restrict__ A, const float* __restrict__ Bm,
    float* __restrict__ C, int M, int N, int K, int klen,
    const float* __restrict__ bias)
{
    __shared__ float As[BM][BK + 1];
    __shared__ float Bs[BK][BN];
    const int tid = threadIdx.x;
    const int m0 = blockIdx.y * BM;
    const int n0 = blockIdx.x * BN;
    const int k0 = blockIdx.z * klen;
    constexpr int NT = 256;
    constexpr int TX = BN / TN;          // threads along N
    const int tx = tid % TX;
    const int ty = tid / TX;

    float c[TM][TN];
#pragma unroll
    for (int i = 0; i < TM; i++)
#pragma unroll
        for (int j = 0; j < TN; j++) c[i][j] = 0.f;

    for (int kb = k0; kb < k0 + klen; kb += BK) {
        // load A tile
#pragma unroll
        for (int i = 0; i < (BM * BK) / NT; i++) {
            int idx = i * NT + tid;
            int m = idx / BK, kk = idx % BK;
            As[m][kk] = A[(size_t)(m0 + m) * K + kb + kk];
        }
        // load B tile (guard N edge)
#pragma unroll
        for (int i = 0; i < (BK * BN) / NT; i++) {
            int idx = i * NT + tid;
            int kk = idx / BN, n = idx % BN;
            float v = 0.f;
            if (n0 + n < N) v = Bm[(size_t)(kb + kk) * N + n0 + n];
            Bs[kk][n] = v;
        }
        __syncthreads();
#pragma unroll
        for (int kk = 0; kk < BK; kk++) {
            float a[TM], b[TN];
#pragma unroll
            for (int i = 0; i < TM; i++) a[i] = As[ty * TM + i][kk];
#pragma unroll
            for (int j = 0; j < TN; j++) b[j] = Bs[kk][tx * TN + j];
#pragma unroll
            for (int i = 0; i < TM; i++)
#pragma unroll
                for (int j = 0; j < TN; j++) c[i][j] += a[i] * b[j];
        }
        __syncthreads();
    }
#pragma unroll
    for (int i = 0; i < TM; i++) {
        int m = m0 + ty * TM + i;
#pragma unroll
        for (int j = 0; j < TN; j++) {
            int n = n0 + tx * TN + j;
            if (n < N) {
                if (MODE == 0) {
                    C[(size_t)m * N + n] = c[i][j] + (bias ? bias[n] : 0.f);
                } else if (MODE == 1) {
                    atomicAdd(&C[(size_t)m * N + n], c[i][j]);
                } else {
                    int bb = m & 63, tt = m >> 6;
                    C[(size_t)(bb * cTS + tt) * N + n] = c[i][j] + bias[n];
                }
            }
        }
    }
}

// ---------------- helpers ----------------
__global__ void k_transpose(const float* __restrict__ in, float* __restrict__ out,
                            int R, int C)
{
    __shared__ float tile[32][33];
    int c0 = blockIdx.x * 32, r0 = blockIdx.y * 32;
#pragma unroll
    for (int i = 0; i < 32; i += 8)
        tile[threadIdx.y + i][threadIdx.x] =
            in[(size_t)(r0 + threadIdx.y + i) * C + c0 + threadIdx.x];
    __syncthreads();
#pragma unroll
    for (int i = 0; i < 32; i += 8)
        out[(size_t)(c0 + threadIdx.y + i) * R + r0 + threadIdx.x] =
            tile[threadIdx.x][threadIdx.y + i];
}

__global__ void k_zero(float* p, int n)
{
    int i = blockIdx.x * blockDim.x + threadIdx.x;
    if (i < n) p[i] = 0.f;
}

__global__ void k_embed(const int* __restrict__ captions, const int* __restrict__ sos,
                        const float* __restrict__ emb)
{
    int r = blockIdx.x;              // r = t*64 + b
    int t = r >> 6, b = r & 63;
    int tok = (t == 0) ? *sos : captions[b * cT + t];
    const float* src = emb + (size_t)tok * cE;
    float* dst = g_xemb + (size_t)r * cE;
    for (int i = threadIdx.x; i < cE; i += blockDim.x) dst[i] = src[i];
}

__global__ void k_initbias(float* C, const float* __restrict__ bias, int N, int total)
{
    int i = blockIdx.x * blockDim.x + threadIdx.x;
    if (i < total) C[i] = bias[i % N];
}

__global__ void k_init2(float* gi, const float* __restrict__ bi,
                        float* gh, const float* __restrict__ bh)
{
    int i = blockIdx.x * blockDim.x + threadIdx.x;
    if (i < cB * 3 * cH) {
        int n = i % (3 * cH);
        gi[i] = bi[n];
        gh[i] = bh[n];
    }
}

// scores: e[b,s] = sum_h tanh(q[b,h] + keys[b,s,h]) * v[h] + bv
__global__ __launch_bounds__(256) void k_scores(const float* __restrict__ v,
                                                const float* __restrict__ bv)
{
    int bs = blockIdx.x;             // b*196 + s
    int b = bs / cS;
    int tid = threadIdx.x;
    const float* qr = g_q + (size_t)b * cH;
    const float* kr = g_keys + (size_t)bs * cH;
    float acc = 0.f;
#pragma unroll 4
    for (int h = tid; h < cH; h += 256)
        acc += tanhf(qr[h] + kr[h]) * v[h];
#pragma unroll
    for (int o = 16; o; o >>= 1) acc += __shfl_down_sync(0xffffffffu, acc, o);
    __shared__ float red[8];
    if ((tid & 31) == 0) red[tid >> 5] = acc;
    __syncthreads();
    if (tid == 0) {
        float s = 0.f;
#pragma unroll
        for (int i = 0; i < 8; i++) s += red[i];
        g_e[bs] = s + bv[0];
    }
}

__global__ __launch_bounds__(256) void k_softmax()
{
    int b = blockIdx.x, tid = threadIdx.x;
    __shared__ float sm[256];
    float v = (tid < cS) ? g_e[b * cS + tid] : -1e30f;
    sm[tid] = v; __syncthreads();
    for (int o = 128; o; o >>= 1) { if (tid < o) sm[tid] = fmaxf(sm[tid], sm[tid + o]); __syncthreads(); }
    float mx = sm[0]; __syncthreads();
    float ev = (tid < cS) ? expf(v - mx) : 0.f;
    sm[tid] = ev; __syncthreads();
    for (int o = 128; o; o >>= 1) { if (tid < o) sm[tid] += sm[tid + o]; __syncthreads(); }
    float s = sm[0];
    if (tid < cS) g_w[b * cS + tid] = ev / s;
}

// ctx into inp[:,H:] (+ copy x_t into inp[:,:H]).  fc0_b is pre-baked into feat0.
__global__ __launch_bounds__(256) void k_ctx(int t)
{
    int idx = blockIdx.x * blockDim.x + threadIdx.x;   // 65536 threads
    int b = idx >> 10, h = idx & (cH - 1);
    const float* f = g_feat0 + ((size_t)b * cS) * cH + h;
    const float* wr = g_w + b * cS;
    float a0 = 0.f, a1 = 0.f, a2 = 0.f, a3 = 0.f;
#pragma unroll 1
    for (int s = 0; s < cS; s += 4) {
        a0 += wr[s + 0] * f[(size_t)(s + 0) * cH];
        a1 += wr[s + 1] * f[(size_t)(s + 1) * cH];
        a2 += wr[s + 2] * f[(size_t)(s + 2) * cH];
        a3 += wr[s + 3] * f[(size_t)(s + 3) * cH];
    }
    g_inp[b * 2 * cH + cH + h] = (a0 + a1) + (a2 + a3);
    g_inp[b * 2 * cH + h] = g_xseq[(size_t)(t * cB + b) * cH + h];
}

__device__ __forceinline__ float sigm(float x) { return 1.f / (1.f + expf(-x)); }

__global__ __launch_bounds__(256) void k_gruew(int layer, int t)
{
    int idx = blockIdx.x * blockDim.x + threadIdx.x;   // 65536
    int b = idx >> 10, j = idx & (cH - 1);
    const float* gi = g_gi + (size_t)b * 3 * cH;
    const float* gh = g_gh + (size_t)b * 3 * cH;
    float ir = gi[j], iz = gi[cH + j], inn = gi[2 * cH + j];
    float hr = gh[j], hz = gh[cH + j], hn = gh[2 * cH + j];
    float r = sigm(ir + hr);
    float z = sigm(iz + hz);
    float n = tanhf(inn + r * hn);
    float* hp = g_h + (size_t)layer * cB * cH + idx;
    float hold = *hp;
    float hnew = (1.f - z) * n + z * hold;
    *hp = hnew;
    if (layer == 3) g_hall[(size_t)(t * cB + b) * cH + j] = hnew;
}

// ---------------- host-side GEMM launcher ----------------
static void gemm(const float* A, const float* Bm, float* C, int M, int N, int K,
                 int splitk, const float* bias, int mode, bool big)
{
    int klen = K / splitk;
    if (big) {
        dim3 g((N + 63) / 64, M / 128, splitk);
        sgemm_k<128, 64, 16, 8, 4, 0><<<g, 256>>>(A, Bm, C, M, N, K, klen, bias);
        return;
    }
    dim3 g((N + 63) / 64, M / 64, splitk);
    if (mode == 0)      sgemm_k<64, 64, 16, 4, 4, 0><<<g, 256>>>(A, Bm, C, M, N, K, klen, bias);
    else if (mode == 1) sgemm_k<64, 64, 16, 4, 4, 1><<<g, 256>>>(A, Bm, C, M, N, K, klen, bias);
    else                sgemm_k<64, 64, 16, 4, 4, 2><<<g, 256>>>(A, Bm, C, M, N, K, klen, bias);
}

extern "C" void kernel_launch(void* const* d_in, const int* in_sizes, int n_in,
                              void* d_out, int out_size)
{
    const float* features = (const float*)d_in[0];
    const int*   captions = (const int*)d_in[1];
    const int*   sos      = (const int*)d_in[2];
    const float* emb      = (const float*)d_in[3];
    const float* fc1_W = (const float*)d_in[4];  const float* fc1_b = (const float*)d_in[5];
    const float* aWq   = (const float*)d_in[6];  const float* abq   = (const float*)d_in[7];
    const float* aWk   = (const float*)d_in[8];  const float* abk   = (const float*)d_in[9];
    const float* av    = (const float*)d_in[10]; const float* abv   = (const float*)d_in[11];
    const float* fc0_W = (const float*)d_in[12]; const float* fc0_b = (const float*)d_in[13];
    const float* Wi0   = (const float*)d_in[14]; const float* Wh0   = (const float*)d_in[15];
    const float* bi0   = (const float*)d_in[16]; const float* bh0   = (const float*)d_in[17];
    const float* Wi    = (const float*)d_in[18]; const float* Wh    = (const float*)d_in[19];
    const float* bi    = (const float*)d_in[20]; const float* bh    = (const float*)d_in[21];
    const float* fc2_W = (const float*)d_in[22]; const float* fc2_b = (const float*)d_in[23];
    float* out = (float*)d_out;

    float *pWi0T, *pWh0T, *pWiT, *pWhT, *pkeys, *pfeat0, *pxemb, *pxseq, *ph,
          *phall, *pq, *pinp, *pgi, *pgh;
    cudaGetSymbolAddress((void**)&pWi0T, g_Wi0T);
    cudaGetSymbolAddress((void**)&pWh0T, g_Wh0T);
    cudaGetSymbolAddress((void**)&pWiT,  g_WiT);
    cudaGetSymbolAddress((void**)&pWhT,  g_WhT);
    cudaGetSymbolAddress((void**)&pkeys, g_keys);
    cudaGetSymbolAddress((void**)&pfeat0, g_feat0);
    cudaGetSymbolAddress((void**)&pxemb, g_xemb);
    cudaGetSymbolAddress((void**)&pxseq, g_xseq);
    cudaGetSymbolAddress((void**)&ph,    g_h);
    cudaGetSymbolAddress((void**)&phall, g_hall);
    cudaGetSymbolAddress((void**)&pq,    g_q);
    cudaGetSymbolAddress((void**)&pinp,  g_inp);
    cudaGetSymbolAddress((void**)&pgi,   g_gi);
    cudaGetSymbolAddress((void**)&pgh,   g_gh);

    dim3 tb(32, 8);
    // one-time weight transposes -> K-major layout
    k_transpose<<<dim3(3 * cH / 32, cK / 32), tb>>>(Wi0, pWi0T, 3 * cH, cK);
    // NOTE: k_transpose(in[R,C]) -> out[C,R]; here in = Wi0 [3H, 2H] (R=3072,C=2048)
    // grid must be (C/32, R/32):
    // (relaunch with correct grid; the first launch above used swapped dims -> fix)
    k_transpose<<<dim3(cK / 32, 3 * cH / 32), tb>>>(Wi0, pWi0T, 3 * cH, cK);
    k_transpose<<<dim3(cH / 32, 3 * cH / 32), tb>>>(Wh0, pWh0T, 3 * cH, cH);
    for (int l = 0; l < 3; l++) {
        k_transpose<<<dim3(cH / 32, 3 * cH / 32), tb>>>(
            Wi + (size_t)l * 3 * cH * cH, pWiT + (size_t)l * cH * 3 * cH, 3 * cH, cH);
        k_transpose<<<dim3(cH / 32, 3 * cH / 32), tb>>>(
            Wh + (size_t)l * 3 * cH * cH, pWhT + (size_t)l * cH * 3 * cH, 3 * cH, cH);
    }

    // init hidden state to zero
    k_zero<<<(4 * cB * cH) / 256, 256>>>(ph, 4 * cB * cH);

    // precompute: x_seq, keys_proj, feat0 (fc0_b baked in: softmax weights sum to 1)
    k_embed<<<MT, 128>>>(captions, sos, emb);
    gemm(pxemb, fc1_W, pxseq, MT, cH, cE, 1, fc1_b, 0, false);
    gemm(features, aWk, pkeys, BSR, cH, cK, 1, abk, 0, true);
    gemm(features, fc0_W, pfeat0, BSR, cH, cK, 1, fc0_b, 0, true);

    for (int t = 0; t < cTS; t++) {
        // q = h[3] @ attn_Wq + bq   (split-K atomic)
        k_initbias<<<(cB * cH) / 256, 256>>>(pq, abq, cH, cB * cH);
        gemm(ph + 3 * cB * cH, aWq, pq, cB, cH, cH, 8, nullptr, 1, false);
        // attention
        k_scores<<<BSR, 256>>>(av, abv);
        k_softmax<<<cB, 256>>>();
        k_ctx<<<(cB * cH) / 256, 256>>>(t);
        // GRU layer 0 (input = [x_t | ctx], K = 2048)
        k_init2<<<(cB * 3 * cH) / 256, 256>>>(pgi, bi0, pgh, bh0);
        gemm(pinp, pWi0T, pgi, cB, 3 * cH, 2 * cH, 4, nullptr, 1, false);
        gemm(ph, pWh0T, pgh, cB, 3 * cH, cH, 4, nullptr, 1, false);
        k_gruew<<<(cB * cH) / 256, 256>>>(0, t);
        // GRU layers 1..3
        for (int l = 1; l < 4; l++) {
            k_init2<<<(cB * 3 * cH) / 256, 256>>>(pgi, bi + (l - 1) * 3 * cH,
                                                  pgh, bh + (l - 1) * 3 * cH);
            gemm(ph + (l - 1) * cB * cH, pWiT + (size_t)(l - 1) * cH * 3 * cH,
                 pgi, cB, 3 * cH, cH, 4, nullptr, 1, false);
            gemm(ph + l * cB * cH, pWhT + (size_t)(l - 1) * cH * 3 * cH,
                 pgh, cB, 3 * cH, cH, 4, nullptr, 1, false);
            k_gruew<<<(cB * cH) / 256, 256>>>(l, t);
        }
    }

    // deferred output projection with row remap (t*64+b -> b*15+t)
    gemm(phall, fc2_W, out, MT, cV, cH, 1, fc2_b, 2, false);
}

// round 4
// speedup vs baseline: 1.2369x; 1.2361x over previous
#include <cuda_runtime.h>
#include <math.h>
#include <stdint.h>

constexpr int cB=64, cS=196, cH=1024, cK=2048, cV=10000, cE=512, cT=16, cTS=15;
constexpr int BSR = cB*cS;            // 12544
constexpr int MT  = cTS*cB;           // 960
constexpr int L0SZ = 128*3072*32;     // packed layer0 weights
constexpr int LSZ  = 128*2048*32;     // packed layers 1..3

__device__ float g_Bp0[L0SZ];
__device__ float g_Bp123[3*LSZ];
__device__ float g_biasp[4*4096];
__device__ float g_keys[BSR*cH];
__device__ float g_feat0[BSR*cH];
__device__ float g_xemb[MT*cE];
__device__ float g_xseq[MT*cH];
__device__ float g_cat0[2*64*3072];
__device__ float g_cat1[2*64*2048];
__device__ float g_cat2[2*64*2048];
__device__ float g_cat3[2*64*2048];
__device__ float g_q[64*1024];
__device__ float g_e[64*cS];
__device__ float g_w[64*cS];
__device__ float g_hall[MT*cH];

__device__ __forceinline__ uint32_t f2tf(float f){
    uint32_t u; asm("cvt.rna.tf32.f32 %0,%1;":"=r"(u):"f"(f)); return u;
}
__device__ __forceinline__ void mma8(float* d, const uint32_t* a, const uint32_t* b){
    asm volatile("mma.sync.aligned.m16n8k8.row.col.f32.tf32.tf32.f32 "
        "{%0,%1,%2,%3},{%4,%5,%6,%7},{%8,%9},{%0,%1,%2,%3};"
        : "+f"(d[0]),"+f"(d[1]),"+f"(d[2]),"+f"(d[3])
        : "r"(a[0]),"r"(a[1]),"r"(a[2]),"r"(a[3]),"r"(b[0]),"r"(b[1]));
}
__device__ __forceinline__ void cpa(void* s, const void* g){
    unsigned sa = (unsigned)__cvta_generic_to_shared(s);
    asm volatile("cp.async.ca.shared.global [%0],[%1],16;"::"r"(sa),"l"(g));
}
__device__ __forceinline__ float sigm(float x){ return 1.f/(1.f+expf(-x)); }
__device__ __forceinline__ float tanha(float x){
    float y; asm("tanh.approx.f32 %0,%1;":"=f"(y):"f"(x)); return y;
}

// ---------- big single-pass tf32 GEMM: C = A[M,K]@B[K,N] + bias ----------
// MODE 0: plain store; MODE 2: fc2 remap row m=t*64+b -> out row b*15+t
template<int MODE>
__global__ __launch_bounds__(256) void k_mm(
    const float* __restrict__ A, const float* __restrict__ B,
    float* __restrict__ C, int M, int N, int K, const float* __restrict__ bias)
{
    __shared__ uint32_t As[128][17];
    __shared__ uint32_t Bs[16][136];
    const int tid=threadIdx.x, w=tid>>5, lane=tid&31, g=lane>>2, cl=lane&3;
    const int m0=blockIdx.y*128, n0=blockIdx.x*128;
    const int wm=(w>>2)*64, wn=(w&3)*32;
    float d[4][4][4];
#pragma unroll
    for(int mi=0;mi<4;mi++)
#pragma unroll
        for(int ni=0;ni<4;ni++)
#pragma unroll
            for(int k=0;k<4;k++) d[mi][ni][k]=0.f;

    for(int kb=0;kb<K;kb+=16){
#pragma unroll
        for(int i=0;i<8;i++){
            int idx=i*256+tid, r=idx>>4, c=idx&15;
            float v=(m0+r<M)?A[(size_t)(m0+r)*K+kb+c]:0.f;
            As[r][c]=f2tf(v);
        }
#pragma unroll
        for(int i=0;i<8;i++){
            int idx=i*256+tid, r=idx>>7, c=idx&127;
            float v=(n0+c<N)?B[(size_t)(kb+r)*N+n0+c]:0.f;
            Bs[r][c]=f2tf(v);
        }
        __syncthreads();
#pragma unroll
        for(int kc=0;kc<16;kc+=8){
            uint32_t a[4][4], b[4][2];
#pragma unroll
            for(int mi=0;mi<4;mi++){
                a[mi][0]=As[wm+16*mi+g][kc+cl];
                a[mi][1]=As[wm+16*mi+8+g][kc+cl];
                a[mi][2]=As[wm+16*mi+g][kc+cl+4];
                a[mi][3]=As[wm+16*mi+8+g][kc+cl+4];
            }
#pragma unroll
            for(int ni=0;ni<4;ni++){
                b[ni][0]=Bs[kc+cl][wn+8*ni+g];
                b[ni][1]=Bs[kc+cl+4][wn+8*ni+g];
            }
#pragma unroll
            for(int mi=0;mi<4;mi++)
#pragma unroll
                for(int ni=0;ni<4;ni++) mma8(d[mi][ni],a[mi],b[ni]);
        }
        __syncthreads();
    }
#pragma unroll
    for(int mi=0;mi<4;mi++)
#pragma unroll
        for(int ni=0;ni<4;ni++)
#pragma unroll
            for(int k=0;k<4;k++){
                int row=m0+wm+16*mi+g+((k>=2)?8:0);
                int col=n0+wn+8*ni+2*cl+(k&1);
                if(row<M && col<N){
                    float v=d[mi][ni][k]+bias[col];
                    if(MODE==0) C[(size_t)row*N+col]=v;
                    else        C[(size_t)((row&63)*cTS+(row>>6))*N+col]=v;
                }
            }
}

// ---------- fused skinny 3xtf32 GEMM (+ optional GRU epilogue) ----------
// A[64,KA] (stride lda). B block = Bg + n*boff, row stride ldb, 32 cols.
// EPI=0: o1[m*ldo1 + n*32+gc] = C + bias[n*32+gc]
// EPI=1: 4-gate GRU update -> o1,o2 at cols n*8+c
template<int EPI>
__global__ __launch_bounds__(256) void k_gru(
    const float* __restrict__ A, int lda, int KA,
    const float* __restrict__ Bg, int ldb, int boff,
    const float* __restrict__ bias,
    const float* __restrict__ hold, int ldh,
    float* __restrict__ o1, int ldo1,
    float* __restrict__ o2, int ldo2)
{
    __shared__ float As[2][64][20];
    __shared__ float Bs[2][16][40];
    __shared__ float Cs[64][36];
    const int n=blockIdx.x, tid=threadIdx.x;
    const float* Bblk = Bg + (size_t)n*boff;
    const int w=tid>>5, lane=tid&31, g=lane>>2, cl=lane&3;
    const int mt=w&3, nh=w>>2;
    const int ar=tid>>2, ach=tid&3;           // A: 64 rows x 4 chunks
    const int br=tid>>3, bch=tid&7;           // B: 16 rows x 8 chunks (tid<128)

    float d[2][4]={{0.f,0.f,0.f,0.f},{0.f,0.f,0.f,0.f}};
    const int nkb = KA/16;

    // prologue: stage 0
    cpa(&As[0][ar][ach*4], A+(size_t)ar*lda+ach*4);
    if(tid<128) cpa(&Bs[0][br][bch*4], Bblk+(size_t)br*ldb+bch*4);
    asm volatile("cp.async.commit_group;");

    for(int i=0;i<nkb;i++){
        int st=i&1;
        if(i+1<nkb){
            int kb=(i+1)*16;
            cpa(&As[st^1][ar][ach*4], A+(size_t)ar*lda+kb+ach*4);
            if(tid<128) cpa(&Bs[st^1][br][bch*4], Bblk+(size_t)(kb+br)*ldb+bch*4);
            asm volatile("cp.async.commit_group;");
            asm volatile("cp.async.wait_group 1;");
        } else {
            asm volatile("cp.async.wait_group 0;");
        }
        __syncthreads();
#pragma unroll
        for(int kc=0;kc<16;kc+=8){
            uint32_t ah[4], al[4];
            float v0=As[st][16*mt+g][kc+cl];
            float v1=As[st][16*mt+8+g][kc+cl];
            float v2=As[st][16*mt+g][kc+cl+4];
            float v3=As[st][16*mt+8+g][kc+cl+4];
            ah[0]=f2tf(v0); al[0]=f2tf(v0-__uint_as_float(ah[0]));
            ah[1]=f2tf(v1); al[1]=f2tf(v1-__uint_as_float(ah[1]));
            ah[2]=f2tf(v2); al[2]=f2tf(v2-__uint_as_float(ah[2]));
            ah[3]=f2tf(v3); al[3]=f2tf(v3-__uint_as_float(ah[3]));
#pragma unroll
            for(int nt=0;nt<2;nt++){
                int ncol=nh*16+nt*8+g;
                float b0=Bs[st][kc+cl][ncol], b1=Bs[st][kc+cl+4][ncol];
                uint32_t bh[2]={f2tf(b0), f2tf(b1)};
                uint32_t bl[2]={f2tf(b0-__uint_as_float(bh[0])),
                                f2tf(b1-__uint_as_float(bh[1]))};
                mma8(d[nt],ah,bh);
                mma8(d[nt],ah,bl);
                mma8(d[nt],al,bh);
            }
        }
        __syncthreads();
    }
#pragma unroll
    for(int nt=0;nt<2;nt++){
        int n0=nh*16+nt*8;
        Cs[16*mt+g][n0+2*cl]     = d[nt][0];
        Cs[16*mt+g][n0+2*cl+1]   = d[nt][1];
        Cs[16*mt+8+g][n0+2*cl]   = d[nt][2];
        Cs[16*mt+8+g][n0+2*cl+1] = d[nt][3];
    }
    __syncthreads();
    if(EPI==0){
#pragma unroll
        for(int i=0;i<8;i++){
            int e=i*256+tid, m=e>>5, gc=e&31;
            o1[(size_t)m*ldo1 + n*32+gc] = Cs[m][gc] + bias[n*32+gc];
        }
    } else {
#pragma unroll
        for(int i=0;i<2;i++){
            int e=i*256+tid, m=e>>3, c=e&7;
            float r_ = sigm(Cs[m][c]    + bias[n*32+c]);
            float z  = sigm(Cs[m][8+c]  + bias[n*32+8+c]);
            float nn = tanhf(Cs[m][16+c] + bias[n*32+16+c]
                             + r_*(Cs[m][24+c] + bias[n*32+24+c]));
            int j=n*8+c;
            float hv=(1.f-z)*nn + z*hold[(size_t)m*ldh+j];
            o1[(size_t)m*ldo1+j]=hv;
            o2[(size_t)m*ldo2+j]=hv;
        }
    }
}

// ---------- attention ----------
__global__ __launch_bounds__(256) void k_scores(const float* __restrict__ v)
{
    int bs=blockIdx.x, b=bs/cS, tid=threadIdx.x;
    const float* qr=g_q+(size_t)b*cH;
    const float* kr=g_keys+(size_t)bs*cH;
    float acc=0.f;
#pragma unroll 4
    for(int h=tid;h<cH;h+=256) acc += tanha(qr[h]+kr[h])*v[h];
#pragma unroll
    for(int o=16;o;o>>=1) acc += __shfl_down_sync(0xffffffffu,acc,o);
    __shared__ float red[8];
    if((tid&31)==0) red[tid>>5]=acc;
    __syncthreads();
    if(tid==0){
        float s=0.f;
#pragma unroll
        for(int i=0;i<8;i++) s+=red[i];
        g_e[bs]=s;
    }
}

__global__ __launch_bounds__(256) void k_softmax()
{
    int b=blockIdx.x, tid=threadIdx.x;
    __shared__ float sm[256];
    float v=(tid<cS)?g_e[b*cS+tid]:-1e30f;
    sm[tid]=v; __syncthreads();
    for(int o=128;o;o>>=1){ if(tid<o) sm[tid]=fmaxf(sm[tid],sm[tid+o]); __syncthreads(); }
    float mx=sm[0]; __syncthreads();
    float ev=(tid<cS)?expf(v-mx):0.f;
    sm[tid]=ev; __syncthreads();
    for(int o=128;o;o>>=1){ if(tid<o) sm[tid]+=sm[tid+o]; __syncthreads(); }
    if(tid<cS) g_w[b*cS+tid]=ev/sm[0];
}

// ctx -> cat0[:,1024:2048], x -> cat0[:,0:1024]
__global__ __launch_bounds__(256) void k_ctx(const float* __restrict__ xrow,
                                             float* __restrict__ cat0p)
{
    int idx=blockIdx.x*blockDim.x+threadIdx.x;  // 65536
    int b=idx>>10, h=idx&(cH-1);
    const float* f=g_feat0+((size_t)b*cS)*cH+h;
    const float* wr=g_w+b*cS;
    float a0=0.f,a1=0.f,a2=0.f,a3=0.f;
#pragma unroll 1
    for(int s=0;s<cS;s+=4){
        a0+=wr[s+0]*f[(size_t)(s+0)*cH];
        a1+=wr[s+1]*f[(size_t)(s+1)*cH];
        a2+=wr[s+2]*f[(size_t)(s+2)*cH];
        a3+=wr[s+3]*f[(size_t)(s+3)*cH];
    }
    cat0p[b*3072+1024+h]=(a0+a1)+(a2+a3);
    cat0p[b*3072+h]=xrow[b*1024+h];
}

// ---------- setup ----------
__global__ void k_embed(const int* __restrict__ captions, const int* __restrict__ sos,
                        const float* __restrict__ emb)
{
    int r=blockIdx.x, t=r>>6, b=r&63;
    int tok=(t==0)?*sos:captions[b*cT+t];
    const float* src=emb+(size_t)tok*cE;
    float* dst=g_xemb+(size_t)r*cE;
    for(int i=threadIdx.x;i<cE;i+=blockDim.x) dst[i]=src[i];
}

__global__ void k_pack0(const float* __restrict__ Wi0, const float* __restrict__ Wh0)
{
    int idx=blockIdx.x*blockDim.x+threadIdx.x;
    if(idx>=L0SZ) return;
    int n=idx/(3072*32), r=idx%(3072*32);
    int k=r>>5, gc=r&31, g=gc>>3, c=gc&7, j=n*8+c;
    float v=0.f;
    if(k<2048){ if(g<3) v=Wi0[(size_t)(g*1024+j)*2048+k]; }
    else { int kh=k-2048;
        if(g<2) v=Wh0[(size_t)(g*1024+j)*1024+kh];
        else if(g==3) v=Wh0[(size_t)(2048+j)*1024+kh]; }
    g_Bp0[idx]=v;
}

__global__ void k_pack123(const float* __restrict__ Wi, const float* __restrict__ Wh)
{
    int z=blockIdx.y;
    int idx=blockIdx.x*blockDim.x+threadIdx.x;
    if(idx>=LSZ) return;
    const float* wi=Wi+(size_t)z*3072*1024;
    const float* wh=Wh+(size_t)z*3072*1024;
    int n=idx/(2048*32), r=idx%(2048*32);
    int k=r>>5, gc=r&31, g=gc>>3, c=gc&7, j=n*8+c;
    float v=0.f;
    if(k<1024){ if(g<3) v=wi[(size_t)(g*1024+j)*1024+k]; }
    else { int kh=k-1024;
        if(g<2) v=wh[(size_t)(g*1024+j)*1024+kh];
        else if(g==3) v=wh[(size_t)(2048+j)*1024+kh]; }
    g_Bp123[(size_t)z*LSZ+idx]=v;
}

__global__ void k_packbias(const float* __restrict__ bi0, const float* __restrict__ bh0,
                           const float* __restrict__ bi, const float* __restrict__ bh)
{
    int idx=blockIdx.x*blockDim.x+threadIdx.x;
    if(idx>=4*4096) return;
    int l=idx>>12, r=idx&4095;
    int n=r>>5, gc=r&31, g=gc>>3, c=gc&7, j=n*8+c;
    const float* bx =(l==0)?bi0:bi+(l-1)*3072;
    const float* bhx=(l==0)?bh0:bh+(l-1)*3072;
    float v;
    if(g==0)      v=bx[j]+bhx[j];
    else if(g==1) v=bx[1024+j]+bhx[1024+j];
    else if(g==2) v=bx[2048+j];
    else          v=bhx[2048+j];
    g_biasp[idx]=v;
}

__global__ void k_zeroh(float* c0,float* c1,float* c2,float* c3)
{
    int idx=blockIdx.x*blockDim.x+threadIdx.x;   // 262144
    if(idx>=4*64*1024) return;
    int reg=idx>>16, q=idx&65535, m=q>>10, j=q&1023;
    if(reg==0)      c0[m*3072+2048+j]=0.f;
    else if(reg==1) c1[m*2048+1024+j]=0.f;
    else if(reg==2) c2[m*2048+1024+j]=0.f;
    else            c3[m*2048+1024+j]=0.f;
}

extern "C" void kernel_launch(void* const* d_in, const int* in_sizes, int n_in,
                              void* d_out, int out_size)
{
    const float* features=(const float*)d_in[0];
    const int*   captions=(const int*)d_in[1];
    const int*   sos     =(const int*)d_in[2];
    const float* emb     =(const float*)d_in[3];
    const float* fc1W=(const float*)d_in[4];  const float* fc1b=(const float*)d_in[5];
    const float* aWq =(const float*)d_in[6];  const float* abq =(const float*)d_in[7];
    const float* aWk =(const float*)d_in[8];  const float* abk =(const float*)d_in[9];
    const float* av  =(const float*)d_in[10];
    const float* fc0W=(const float*)d_in[12]; const float* fc0b=(const float*)d_in[13];
    const float* Wi0 =(const float*)d_in[14]; const float* Wh0 =(const float*)d_in[15];
    const float* bi0 =(const float*)d_in[16]; const float* bh0 =(const float*)d_in[17];
    const float* Wi  =(const float*)d_in[18]; const float* Wh  =(const float*)d_in[19];
    const float* bi  =(const float*)d_in[20]; const float* bh  =(const float*)d_in[21];
    const float* fc2W=(const float*)d_in[22]; const float* fc2b=(const float*)d_in[23];
    float* out=(float*)d_out;

    float *pBp0,*pBp123,*pbias,*pkeys,*pfeat0,*pxemb,*pxseq,*pc0,*pc1,*pc2,*pc3,*pq,*phall;
    cudaGetSymbolAddress((void**)&pBp0,  g_Bp0);
    cudaGetSymbolAddress((void**)&pBp123,g_Bp123);
    cudaGetSymbolAddress((void**)&pbias, g_biasp);
    cudaGetSymbolAddress((void**)&pkeys, g_keys);
    cudaGetSymbolAddress((void**)&pfeat0,g_feat0);
    cudaGetSymbolAddress((void**)&pxemb, g_xemb);
    cudaGetSymbolAddress((void**)&pxseq, g_xseq);
    cudaGetSymbolAddress((void**)&pc0,   g_cat0);
    cudaGetSymbolAddress((void**)&pc1,   g_cat1);
    cudaGetSymbolAddress((void**)&pc2,   g_cat2);
    cudaGetSymbolAddress((void**)&pc3,   g_cat3);
    cudaGetSymbolAddress((void**)&pq,    g_q);
    cudaGetSymbolAddress((void**)&phall, g_hall);

    k_pack0<<<L0SZ/256,256>>>(Wi0,Wh0);
    k_pack123<<<dim3(LSZ/256,3),256>>>(Wi,Wh);
    k_packbias<<<64,256>>>(bi0,bh0,bi,bh);
    k_zeroh<<<1024,256>>>(pc0,pc1,pc2,pc3);
    k_embed<<<MT,128>>>(captions,sos,emb);
    k_mm<0><<<dim3(8,8),256>>>(pxemb,fc1W,pxseq,MT,cH,cE,fc1b);
    k_mm<0><<<dim3(8,98),256>>>(features,aWk,pkeys,BSR,cH,cK,abk);
    k_mm<0><<<dim3(8,98),256>>>(features,fc0W,pfeat0,BSR,cH,cK,fc0b);

    for(int t=0;t<cTS;t++){
        int p=t&1, pp=p^1;
        float *c0=pc0+p*64*3072, *d0=pc0+pp*64*3072;
        float *c1=pc1+p*64*2048, *d1=pc1+pp*64*2048;
        float *c2=pc2+p*64*2048, *d2=pc2+pp*64*2048;
        float *c3=pc3+p*64*2048, *d3=pc3+pp*64*2048;
        // q = h3 @ Wq + bq   (3xtf32)
        k_gru<0><<<32,256>>>(c3+1024,2048,1024, aWq,1024,32, abq,
                             (const float*)0,0, pq,1024, pq,1024);
        k_scores<<<BSR,256>>>(av);
        k_softmax<<<64,256>>>();
        k_ctx<<<256,256>>>(pxseq+(size_t)t*64*1024, c0);
        // GRU stack
        k_gru<1><<<128,256>>>(c0,3072,3072, pBp0,32,3072*32, pbias,
                              c0+2048,3072, d0+2048,3072, c1,2048);
        k_gru<1><<<128,256>>>(c1,2048,2048, pBp123,32,2048*32, pbias+4096,
                              c1+1024,2048, d1+1024,2048, c2,2048);
        k_gru<1><<<128,256>>>(c2,2048,2048, pBp123+LSZ,32,2048*32, pbias+8192,
                              c2+1024,2048, d2+1024,2048, c3,2048);
        k_gru<1><<<128,256>>>(c3,2048,2048, pBp123+2*LSZ,32,2048*32, pbias+12288,
                              c3+1024,2048, d3+1024,2048, phall+(size_t)t*64*1024,1024);
    }
    // deferred fc2 with row remap
    k_mm<2><<<dim3(79,8),256>>>(phall,fc2W,out,MT,cV,cH,fc2b);
}